// round 8
// baseline (speedup 1.0000x reference)
#include <cuda_runtime.h>
#include <cuda_bf16.h>
#include <cstdint>

// Problem constants
#define Bc 4
#define Hc 16
#define Sc 2048
#define Dc 1024
#define DHc 64
#define Mrows (Bc*Sc)          // 8192

// Scratch (device globals; allocation is forbidden)
__device__ float g_q[Bc*Hc*Sc*DHc];   // [B,H,S,DH]
__device__ float g_k[Bc*Hc*Sc*DHc];
__device__ float g_v[Bc*Hc*Sc*DHc];
__device__ float g_o[Bc*Sc*Dc];       // [B,S,D] attention output

// ===========================================================================
// HMMA helpers (mma.sync path — tcgen05 is unavailable: harness compiles via
// virtual arch compute_103, which lacks the sm_103a feature suffix)
// ===========================================================================
__device__ __forceinline__ uint32_t smem_u32(const void* p) {
    uint32_t a;
    asm("{ .reg .u64 t; cvta.to.shared.u64 t, %1; cvt.u32.u64 %0, t; }"
        : "=r"(a) : "l"(p));
    return a;
}

__device__ __forceinline__ void ldsm_x4(uint32_t* r, uint32_t addr) {
    asm volatile("ldmatrix.sync.aligned.m8n8.x4.shared.b16 {%0,%1,%2,%3}, [%4];"
        : "=r"(r[0]), "=r"(r[1]), "=r"(r[2]), "=r"(r[3]) : "r"(addr));
}
__device__ __forceinline__ void ldsm_x2(uint32_t* r, uint32_t addr) {
    asm volatile("ldmatrix.sync.aligned.m8n8.x2.shared.b16 {%0,%1}, [%2];"
        : "=r"(r[0]), "=r"(r[1]) : "r"(addr));
}
__device__ __forceinline__ void mma16816(float* c, const uint32_t* a, const uint32_t* b) {
    asm volatile("mma.sync.aligned.m16n8k16.row.col.f32.bf16.bf16.f32 "
        "{%0,%1,%2,%3}, {%4,%5,%6,%7}, {%8,%9}, {%0,%1,%2,%3};"
        : "+f"(c[0]), "+f"(c[1]), "+f"(c[2]), "+f"(c[3])
        : "r"(a[0]), "r"(a[1]), "r"(a[2]), "r"(a[3]), "r"(b[0]), "r"(b[1]));
}

// ===========================================================================
// Split-bf16 NT GEMM on HMMA: C[m,n] = sum_k A[m,k]*B[n,k] + bias[n]
// 3-term split: a = hi(trunc bf16) + lo(rn bf16); D += AhBh + AhBl + AlBh.
// Block 128x128, BK=32 (fp32), 8 warps (2M x 4N -> 64x32 warp tile),
// 2-stage smem double buffer + register prefetch.
// smem tiles: bf16, row stride 40 b16 (80B) -> conflict-free ldmatrix.
// mode 0: row-major C.  mode 1: QKV scatter into g_q/g_k/g_v.
// ===========================================================================
#define RS 80                   // row stride bytes
#define TILE_BYTES (128*RS)     // 10240
#define STG_BYTES  (4*TILE_BYTES)  // Ahi,Alo,Bhi,Blo = 40960
#define GSMEM_TOTAL (2*STG_BYTES)  // 81920

__global__ __launch_bounds__(256, 1)
void gemm_hmma(const float* __restrict__ A, const float* __restrict__ Bw,
               const float* __restrict__ bias, float* __restrict__ C,
               int M, int N, int K, int mode)
{
    extern __shared__ char smem[];
    const uint32_t sb = smem_u32(smem);
    const int tid  = threadIdx.x;
    const int wid  = tid >> 5;
    const int lane = tid & 31;
    const int m0 = blockIdx.y * 128;
    const int n0 = blockIdx.x * 128;
    const int warpM = wid & 1;         // 0..1
    const int warpN = wid >> 1;        // 0..3

    float acc[4][4][4];
#pragma unroll
    for (int i = 0; i < 4; i++)
#pragma unroll
        for (int j = 0; j < 4; j++)
#pragma unroll
            for (int q = 0; q < 4; q++) acc[i][j][q] = 0.f;

    const int nch = K >> 5;            // K chunks of 32

    // per-thread load coords: 1024 float4 per tile, 4 per thread
    const int lrow = tid >> 1;                    // reused below differently
    (void)lrow;

    float4 pa[4], pb[4];

    auto load_chunk = [&](int c) {
#pragma unroll
        for (int it = 0; it < 4; ++it) {
            const int idx = it * 256 + tid;       // 0..1023
            const int row = idx >> 3;             // 0..127
            const int c4  = idx & 7;              // 0..7 (float4 col)
            pa[it] = *(const float4*)(A + (size_t)(m0 + row) * K + c * 32 + c4 * 4);
            pb[it] = *(const float4*)(Bw + (size_t)(n0 + row) * K + c * 32 + c4 * 4);
        }
    };

    auto split_store = [&](uint32_t hiT, uint32_t loT, const float4& v, uint32_t off) {
        uint32_t bx = __float_as_uint(v.x), by = __float_as_uint(v.y),
                 bz = __float_as_uint(v.z), bw = __float_as_uint(v.w);
        uint32_t hi01 = __byte_perm(bx, by, 0x7632);
        uint32_t hi23 = __byte_perm(bz, bw, 0x7632);
        float lx = v.x - __uint_as_float(bx & 0xFFFF0000u);
        float ly = v.y - __uint_as_float(by & 0xFFFF0000u);
        float lz = v.z - __uint_as_float(bz & 0xFFFF0000u);
        float lw = v.w - __uint_as_float(bw & 0xFFFF0000u);
        __nv_bfloat162 l01 = __floats2bfloat162_rn(lx, ly);
        __nv_bfloat162 l23 = __floats2bfloat162_rn(lz, lw);
        asm volatile("st.shared.v2.b32 [%0], {%1, %2};"
                     :: "r"(hiT + off), "r"(hi01), "r"(hi23));
        asm volatile("st.shared.v2.b32 [%0], {%1, %2};"
                     :: "r"(loT + off), "r"(*(uint32_t*)&l01), "r"(*(uint32_t*)&l23));
    };

    auto store_chunk = [&](int s) {
        const uint32_t st  = sb + s * STG_BYTES;
        const uint32_t sAh = st, sAl = st + TILE_BYTES,
                       sBh = st + 2*TILE_BYTES, sBl = st + 3*TILE_BYTES;
#pragma unroll
        for (int it = 0; it < 4; ++it) {
            const int idx = it * 256 + tid;
            const int row = idx >> 3;
            const int c4  = idx & 7;
            const uint32_t off = row * RS + c4 * 8;
            split_store(sAh, sAl, pa[it], off);
            split_store(sBh, sBl, pb[it], off);
        }
    };

    load_chunk(0);
    store_chunk(0);
    __syncthreads();

    for (int c = 0; c < nch; ++c) {
        if (c + 1 < nch) load_chunk(c + 1);

        const uint32_t st  = sb + (c & 1) * STG_BYTES;
        const uint32_t sAh = st, sAl = st + TILE_BYTES,
                       sBh = st + 2*TILE_BYTES, sBl = st + 3*TILE_BYTES;

#pragma unroll
        for (int ks = 0; ks < 2; ++ks) {
            uint32_t ah[4][4], al[4][4], bh[4][2], bl[4][2];
            const uint32_t aRowOff = (warpM * 64 + (lane & 15)) * RS + ks * 32 + (lane >> 4) * 16;
            const uint32_t bRowOff = (warpN * 32 + (lane & 7)) * RS + ks * 32 + ((lane >> 3) & 1) * 16;
#pragma unroll
            for (int mi = 0; mi < 4; ++mi) {
                ldsm_x4(ah[mi], sAh + aRowOff + mi * 16 * RS);
                ldsm_x4(al[mi], sAl + aRowOff + mi * 16 * RS);
            }
#pragma unroll
            for (int ni = 0; ni < 4; ++ni) {
                ldsm_x2(bh[ni], sBh + bRowOff + ni * 8 * RS);
                ldsm_x2(bl[ni], sBl + bRowOff + ni * 8 * RS);
            }
#pragma unroll
            for (int mi = 0; mi < 4; ++mi)
#pragma unroll
                for (int ni = 0; ni < 4; ++ni) {
                    mma16816(acc[mi][ni], ah[mi], bh[ni]);
                    mma16816(acc[mi][ni], ah[mi], bl[ni]);
                    mma16816(acc[mi][ni], al[mi], bh[ni]);
                }
        }

        if (c + 1 < nch) store_chunk((c + 1) & 1);
        __syncthreads();
    }

    // Epilogue: per-warp 64x32 tile; thread holds 2x2 per (mi,ni) frag.
#pragma unroll
    for (int mi = 0; mi < 4; ++mi) {
#pragma unroll
        for (int ni = 0; ni < 4; ++ni) {
            const int gm = m0 + warpM * 64 + mi * 16 + (lane >> 2);
            const int gn = n0 + warpN * 32 + ni * 8 + (lane & 3) * 2;
            const float b0 = __ldg(bias + gn);
            const float b1 = __ldg(bias + gn + 1);
            float v00 = acc[mi][ni][0] + b0, v01 = acc[mi][ni][1] + b1;
            float v10 = acc[mi][ni][2] + b0, v11 = acc[mi][ni][3] + b1;
            if (mode == 0) {
                *(float2*)(C + (size_t)gm * N + gn)       = make_float2(v00, v01);
                *(float2*)(C + (size_t)(gm + 8) * N + gn) = make_float2(v10, v11);
            } else {
                const int h   = gn / 192;
                const int rmd = gn - h * 192;
                const int which = rmd >> 6;
                const int dh = rmd & 63;
                float* base = (which == 0) ? g_q : (which == 1) ? g_k : g_v;
                const int b_0 = gm >> 11, s_0 = gm & 2047;
                const int b_1 = (gm + 8) >> 11, s_1 = (gm + 8) & 2047;
                *(float2*)(base + (((size_t)(b_0 * Hc + h)) * Sc + s_0) * DHc + dh) = make_float2(v00, v01);
                *(float2*)(base + (((size_t)(b_1 * Hc + h)) * Sc + s_1) * DHc + dh) = make_float2(v10, v11);
            }
        }
    }
}

// ===========================================================================
// Flash-style attention with ALiBi (SIMT, unchanged)
// ===========================================================================
__global__ __launch_bounds__(128) void attn_kernel(const float* __restrict__ alibi)
{
    __shared__ float Qs[32][65];
    __shared__ float Ks[64][65];
    __shared__ float Vs[64][65];
    __shared__ float Ps[32][65];

    const int tid = threadIdx.x;
    const int blk = blockIdx.x;
    const int qt  = blk & 63;
    const int bh  = blk >> 6;
    const int h   = bh & 15;
    const int b   = bh >> 4;
    const int q0  = qt * 32;

    const float* Qg = g_q + ((size_t)bh * Sc + q0) * DHc;
    const float* Kg = g_k + (size_t)bh * Sc * DHc;
    const float* Vg = g_v + (size_t)bh * Sc * DHc;
    const float* Ag = alibi + ((size_t)h * Sc + q0) * Sc;

    for (int i = tid; i < 32 * 64; i += 128)
        Qs[i >> 6][i & 63] = Qg[i];

    const int qb = (tid >> 3) * 2;
    const int kg = tid & 7;
    const int d0 = kg * 8;

    float m0 = -1e30f, m1 = -1e30f, l0 = 0.f, l1 = 0.f;
    float acc0[8], acc1[8];
#pragma unroll
    for (int i = 0; i < 8; i++) { acc0[i] = 0.f; acc1[i] = 0.f; }

    for (int c = 0; c < Sc; c += 64) {
        __syncthreads();
        for (int i = tid; i < 64 * 64; i += 128) {
            const int r = i >> 6, cc = i & 63;
            Ks[r][cc] = Kg[c * 64 + i];
            Vs[r][cc] = Vg[c * 64 + i];
        }
        for (int i = tid; i < 32 * 64; i += 128)
            Ps[i >> 6][i & 63] = Ag[(size_t)(i >> 6) * Sc + c + (i & 63)];
        __syncthreads();

        float s0[8], s1[8];
#pragma unroll
        for (int kk = 0; kk < 8; kk++) { s0[kk] = 0.f; s1[kk] = 0.f; }
#pragma unroll 8
        for (int d = 0; d < 64; d++) {
            const float qv0 = Qs[qb][d];
            const float qv1 = Qs[qb + 1][d];
#pragma unroll
            for (int kk = 0; kk < 8; kk++) {
                const float kv = Ks[kg * 8 + kk][d];
                s0[kk] += qv0 * kv;
                s1[kk] += qv1 * kv;
            }
        }
        float mx0 = -1e30f, mx1 = -1e30f;
#pragma unroll
        for (int kk = 0; kk < 8; kk++) {
            s0[kk] = s0[kk] * 0.125f + Ps[qb][kg * 8 + kk];
            s1[kk] = s1[kk] * 0.125f + Ps[qb + 1][kg * 8 + kk];
            mx0 = fmaxf(mx0, s0[kk]);
            mx1 = fmaxf(mx1, s1[kk]);
        }
#pragma unroll
        for (int off = 4; off; off >>= 1) {
            mx0 = fmaxf(mx0, __shfl_xor_sync(0xffffffffu, mx0, off));
            mx1 = fmaxf(mx1, __shfl_xor_sync(0xffffffffu, mx1, off));
        }
        const float mn0 = fmaxf(m0, mx0);
        const float mn1 = fmaxf(m1, mx1);
        float sum0 = 0.f, sum1 = 0.f;
#pragma unroll
        for (int kk = 0; kk < 8; kk++) {
            const float p0 = __expf(s0[kk] - mn0);
            const float p1 = __expf(s1[kk] - mn1);
            Ps[qb][kg * 8 + kk]     = p0;
            Ps[qb + 1][kg * 8 + kk] = p1;
            sum0 += p0; sum1 += p1;
        }
#pragma unroll
        for (int off = 4; off; off >>= 1) {
            sum0 += __shfl_xor_sync(0xffffffffu, sum0, off);
            sum1 += __shfl_xor_sync(0xffffffffu, sum1, off);
        }
        const float c0 = __expf(m0 - mn0);
        const float c1 = __expf(m1 - mn1);
        l0 = l0 * c0 + sum0;
        l1 = l1 * c1 + sum1;
        m0 = mn0; m1 = mn1;
#pragma unroll
        for (int i = 0; i < 8; i++) { acc0[i] *= c0; acc1[i] *= c1; }
        __syncthreads();

#pragma unroll 8
        for (int k = 0; k < 64; k++) {
            const float p0 = Ps[qb][k];
            const float p1 = Ps[qb + 1][k];
#pragma unroll
            for (int i = 0; i < 8; i++) {
                const float vv = Vs[k][d0 + i];
                acc0[i] += p0 * vv;
                acc1[i] += p1 * vv;
            }
        }
    }

    const float inv0 = 1.f / l0;
    const float inv1 = 1.f / l1;
    float* dst0 = g_o + ((size_t)(b * Sc + q0 + qb)) * Dc + h * DHc + d0;
    float* dst1 = dst0 + Dc;
#pragma unroll
    for (int i = 0; i < 8; i++) {
        dst0[i] = acc0[i] * inv0;
        dst1[i] = acc1[i] * inv1;
    }
}

// ===========================================================================
// kernel_launch: x, alibi, w_qkv, b_qkv, w_o, b_o (all fp32)
// ===========================================================================
extern "C" void kernel_launch(void* const* d_in, const int* in_sizes, int n_in,
                              void* d_out, int out_size)
{
    const float* x     = (const float*)d_in[0];
    const float* alibi = (const float*)d_in[1];
    const float* w_qkv = (const float*)d_in[2];
    const float* b_qkv = (const float*)d_in[3];
    const float* w_o   = (const float*)d_in[4];
    const float* b_o   = (const float*)d_in[5];
    float* out = (float*)d_out;

    cudaFuncSetAttribute(gemm_hmma, cudaFuncAttributeMaxDynamicSharedMemorySize, GSMEM_TOTAL);

    // 1) QKV projection: [8192,1024] x [3072,1024]^T -> q/k/v scatter
    {
        dim3 grid(3 * Dc / 128, Mrows / 128);   // (24, 64)
        gemm_hmma<<<grid, 256, GSMEM_TOTAL>>>(x, w_qkv, b_qkv, nullptr,
                                              Mrows, 3 * Dc, Dc, 1);
    }

    // 2) Attention (flash-style SIMT)
    {
        dim3 grid(Bc * Hc * (Sc / 32));          // 4096
        attn_kernel<<<grid, 128>>>(alibi);
    }

    // 3) Output projection: [8192,1024] x [1024,1024]^T + b_o -> out
    {
        float* o_src;
        cudaGetSymbolAddress((void**)&o_src, g_o);
        dim3 grid(Dc / 128, Mrows / 128);        // (8, 64)
        gemm_hmma<<<grid, 256, GSMEM_TOTAL>>>(o_src, w_o, b_o, out,
                                              Mrows, Dc, Dc, 0);
    }
}

// round 9
// speedup vs baseline: 3.8862x; 3.8862x over previous
#include <cuda_runtime.h>
#include <cuda_bf16.h>
#include <cstdint>

// Problem constants
#define Bc 4
#define Hc 16
#define Sc 2048
#define Dc 1024
#define DHc 64
#define Mrows (Bc*Sc)          // 8192

// Scratch (device globals; allocation is forbidden)
// q/k/v stored as split bf16: value = hi (truncated) + lo (rn of residual)
__device__ __nv_bfloat16 g_qh[Bc*Hc*Sc*DHc];
__device__ __nv_bfloat16 g_ql[Bc*Hc*Sc*DHc];
__device__ __nv_bfloat16 g_kh[Bc*Hc*Sc*DHc];
__device__ __nv_bfloat16 g_kl[Bc*Hc*Sc*DHc];
__device__ __nv_bfloat16 g_vh[Bc*Hc*Sc*DHc];
__device__ __nv_bfloat16 g_vl[Bc*Hc*Sc*DHc];
__device__ float g_o[Bc*Sc*Dc];       // [B,S,D] attention output (fp32)

// ===========================================================================
// HMMA helpers (mma.sync path — tcgen05 unavailable through compute_103)
// ===========================================================================
__device__ __forceinline__ uint32_t smem_u32(const void* p) {
    uint32_t a;
    asm("{ .reg .u64 t; cvta.to.shared.u64 t, %1; cvt.u32.u64 %0, t; }"
        : "=r"(a) : "l"(p));
    return a;
}
__device__ __forceinline__ void ldsm_x4(uint32_t* r, uint32_t addr) {
    asm volatile("ldmatrix.sync.aligned.m8n8.x4.shared.b16 {%0,%1,%2,%3}, [%4];"
        : "=r"(r[0]), "=r"(r[1]), "=r"(r[2]), "=r"(r[3]) : "r"(addr));
}
__device__ __forceinline__ void ldsm_x2(uint32_t* r, uint32_t addr) {
    asm volatile("ldmatrix.sync.aligned.m8n8.x2.shared.b16 {%0,%1}, [%2];"
        : "=r"(r[0]), "=r"(r[1]) : "r"(addr));
}
__device__ __forceinline__ void ldsm_x2t(uint32_t* r, uint32_t addr) {
    asm volatile("ldmatrix.sync.aligned.m8n8.x2.trans.shared.b16 {%0,%1}, [%2];"
        : "=r"(r[0]), "=r"(r[1]) : "r"(addr));
}
__device__ __forceinline__ void mma16816(float* c, const uint32_t* a, const uint32_t* b) {
    asm volatile("mma.sync.aligned.m16n8k16.row.col.f32.bf16.bf16.f32 "
        "{%0,%1,%2,%3}, {%4,%5,%6,%7}, {%8,%9}, {%0,%1,%2,%3};"
        : "+f"(c[0]), "+f"(c[1]), "+f"(c[2]), "+f"(c[3])
        : "r"(a[0]), "r"(a[1]), "r"(a[2]), "r"(a[3]), "r"(b[0]), "r"(b[1]));
}
#define CP16(dst, src) \
    asm volatile("cp.async.cg.shared.global [%0], [%1], 16;" :: "r"(dst), "l"(src))
#define CP_COMMIT() asm volatile("cp.async.commit_group;" ::: "memory")
#define CP_WAIT(n)  asm volatile("cp.async.wait_group %0;" :: "n"(n) : "memory")

// split fp32 -> (hi trunc-bf16 as float-bits-high, lo rn-bf16)
__device__ __forceinline__ void pack_pair(float a, float b, uint32_t& hi, uint32_t& lo) {
    const uint32_t ua = __float_as_uint(a), ub = __float_as_uint(b);
    hi = __byte_perm(ua, ub, 0x7632);
    const float la = a - __uint_as_float(ua & 0xFFFF0000u);
    const float lb = b - __uint_as_float(ub & 0xFFFF0000u);
    __nv_bfloat162 l2 = __floats2bfloat162_rn(la, lb);
    lo = *(uint32_t*)&l2;
}

// ===========================================================================
// Split-bf16 NT GEMM on HMMA (unchanged structure): C = A*B^T + bias
// mode 0: row-major C.  mode 1: QKV scatter -> split bf16 q/k/v arrays.
// ===========================================================================
#define RS 80
#define TILE_BYTES (128*RS)
#define STG_BYTES  (4*TILE_BYTES)
#define GSMEM_TOTAL (2*STG_BYTES)

__global__ __launch_bounds__(256, 1)
void gemm_hmma(const float* __restrict__ A, const float* __restrict__ Bw,
               const float* __restrict__ bias, float* __restrict__ C,
               int M, int N, int K, int mode)
{
    extern __shared__ char smem[];
    const uint32_t sb = smem_u32(smem);
    const int tid  = threadIdx.x;
    const int wid  = tid >> 5;
    const int lane = tid & 31;
    const int m0 = blockIdx.y * 128;
    const int n0 = blockIdx.x * 128;
    const int warpM = wid & 1;
    const int warpN = wid >> 1;

    float acc[4][4][4];
#pragma unroll
    for (int i = 0; i < 4; i++)
#pragma unroll
        for (int j = 0; j < 4; j++)
#pragma unroll
            for (int q = 0; q < 4; q++) acc[i][j][q] = 0.f;

    const int nch = K >> 5;
    float4 pa[4], pb[4];

    auto load_chunk = [&](int c) {
#pragma unroll
        for (int it = 0; it < 4; ++it) {
            const int idx = it * 256 + tid;
            const int row = idx >> 3;
            const int c4  = idx & 7;
            pa[it] = *(const float4*)(A + (size_t)(m0 + row) * K + c * 32 + c4 * 4);
            pb[it] = *(const float4*)(Bw + (size_t)(n0 + row) * K + c * 32 + c4 * 4);
        }
    };
    auto split_store = [&](uint32_t hiT, uint32_t loT, const float4& v, uint32_t off) {
        uint32_t h01, l01, h23, l23;
        pack_pair(v.x, v.y, h01, l01);
        pack_pair(v.z, v.w, h23, l23);
        asm volatile("st.shared.v2.b32 [%0], {%1, %2};" :: "r"(hiT + off), "r"(h01), "r"(h23));
        asm volatile("st.shared.v2.b32 [%0], {%1, %2};" :: "r"(loT + off), "r"(l01), "r"(l23));
    };
    auto store_chunk = [&](int s) {
        const uint32_t st  = sb + s * STG_BYTES;
        const uint32_t sAh = st, sAl = st + TILE_BYTES,
                       sBh = st + 2*TILE_BYTES, sBl = st + 3*TILE_BYTES;
#pragma unroll
        for (int it = 0; it < 4; ++it) {
            const int idx = it * 256 + tid;
            const int row = idx >> 3;
            const int c4  = idx & 7;
            const uint32_t off = row * RS + c4 * 8;
            split_store(sAh, sAl, pa[it], off);
            split_store(sBh, sBl, pb[it], off);
        }
    };

    load_chunk(0);
    store_chunk(0);
    __syncthreads();

    for (int c = 0; c < nch; ++c) {
        if (c + 1 < nch) load_chunk(c + 1);

        const uint32_t st  = sb + (c & 1) * STG_BYTES;
        const uint32_t sAh = st, sAl = st + TILE_BYTES,
                       sBh = st + 2*TILE_BYTES, sBl = st + 3*TILE_BYTES;

#pragma unroll
        for (int ks = 0; ks < 2; ++ks) {
            uint32_t ah[4][4], al[4][4], bh[4][2], bl[4][2];
            const uint32_t aRowOff = (warpM * 64 + (lane & 15)) * RS + ks * 32 + (lane >> 4) * 16;
            const uint32_t bRowOff = (warpN * 32 + (lane & 7)) * RS + ks * 32 + ((lane >> 3) & 1) * 16;
#pragma unroll
            for (int mi = 0; mi < 4; ++mi) {
                ldsm_x4(ah[mi], sAh + aRowOff + mi * 16 * RS);
                ldsm_x4(al[mi], sAl + aRowOff + mi * 16 * RS);
            }
#pragma unroll
            for (int ni = 0; ni < 4; ++ni) {
                ldsm_x2(bh[ni], sBh + bRowOff + ni * 8 * RS);
                ldsm_x2(bl[ni], sBl + bRowOff + ni * 8 * RS);
            }
#pragma unroll
            for (int mi = 0; mi < 4; ++mi)
#pragma unroll
                for (int ni = 0; ni < 4; ++ni) {
                    mma16816(acc[mi][ni], ah[mi], bh[ni]);
                    mma16816(acc[mi][ni], ah[mi], bl[ni]);
                    mma16816(acc[mi][ni], al[mi], bh[ni]);
                }
        }

        if (c + 1 < nch) store_chunk((c + 1) & 1);
        __syncthreads();
    }

#pragma unroll
    for (int mi = 0; mi < 4; ++mi) {
#pragma unroll
        for (int ni = 0; ni < 4; ++ni) {
            const int gm = m0 + warpM * 64 + mi * 16 + (lane >> 2);
            const int gn = n0 + warpN * 32 + ni * 8 + (lane & 3) * 2;
            const float b0 = __ldg(bias + gn);
            const float b1 = __ldg(bias + gn + 1);
            float v00 = acc[mi][ni][0] + b0, v01 = acc[mi][ni][1] + b1;
            float v10 = acc[mi][ni][2] + b0, v11 = acc[mi][ni][3] + b1;
            if (mode == 0) {
                *(float2*)(C + (size_t)gm * N + gn)       = make_float2(v00, v01);
                *(float2*)(C + (size_t)(gm + 8) * N + gn) = make_float2(v10, v11);
            } else {
                const int h   = gn / 192;
                const int rmd = gn - h * 192;
                const int which = rmd >> 6;
                const int dh = rmd & 63;
                __nv_bfloat16* baseH = (which == 0) ? g_qh : (which == 1) ? g_kh : g_vh;
                __nv_bfloat16* baseL = (which == 0) ? g_ql : (which == 1) ? g_kl : g_vl;
                const int b_0 = gm >> 11, s_0 = gm & 2047;
                const int b_1 = (gm + 8) >> 11, s_1 = (gm + 8) & 2047;
                const size_t i0 = (((size_t)(b_0 * Hc + h)) * Sc + s_0) * DHc + dh;
                const size_t i1 = (((size_t)(b_1 * Hc + h)) * Sc + s_1) * DHc + dh;
                uint32_t h0, l0, h1, l1;
                pack_pair(v00, v01, h0, l0);
                pack_pair(v10, v11, h1, l1);
                *(uint32_t*)&baseH[i0] = h0;
                *(uint32_t*)&baseL[i0] = l0;
                *(uint32_t*)&baseH[i1] = h1;
                *(uint32_t*)&baseL[i1] = l1;
            }
        }
    }
}

// ===========================================================================
// HMMA FlashAttention with ALiBi.
// Block: 256 threads (8 warps), 128 queries of one (b,h); warp w owns 16 q.
// K/V streamed in 64-key tiles (split bf16) via cp.async double buffer.
// Scores: QhKh+QhKl+QlKh; PV: PhVh+PhVl+PlVh. Register online softmax.
// SMEM (128B rows, xor-swizzled): Qh[0,16K) Ql[16K,32K)
//   stage s at 32K+s*32K: Kh +0, Kl +8K, Vh +16K, Vl +24K. Total 96KB.
// ===========================================================================
#define ASM_QH 0
#define ASM_QL 16384
#define ASM_ST 32768
#define ASM_STRIDE 32768
#define ASM_TOTAL 98304
#define NIT (Sc/64)     // 32

__global__ __launch_bounds__(256, 1)
void attn_hmma(const float* __restrict__ alibi)
{
    extern __shared__ char smem[];
    const uint32_t sb = smem_u32(smem);
    const int tid = threadIdx.x;
    const int wid = tid >> 5;
    const int lane = tid & 31;

    const int qt = blockIdx.x & 15;       // 16 query tiles of 128
    const int bh = blockIdx.x >> 4;       // 0..63
    const int h  = bh & 15;
    const int b  = bh >> 4;
    const int q0 = qt * 128;

    // ---- load Q tile (128 x 64, hi+lo) into swizzled smem ----
    {
        const uint4* gqh = ((const uint4*)g_qh) + ((size_t)bh * Sc + q0) * 8;
        const uint4* gql = ((const uint4*)g_ql) + ((size_t)bh * Sc + q0) * 8;
        for (int i = tid; i < 1024; i += 256) {
            const int row = i >> 3, seg = i & 7;
            const uint32_t soff = row * 128 + ((seg ^ (row & 7)) << 4);
            *(uint4*)(smem + ASM_QH + soff) = gqh[i];
            *(uint4*)(smem + ASM_QL + soff) = gql[i];
        }
    }

    // ---- cp.async producer for K/V tiles ----
    const uint4* gkh = ((const uint4*)g_kh) + (size_t)bh * Sc * 8;
    const uint4* gkl = ((const uint4*)g_kl) + (size_t)bh * Sc * 8;
    const uint4* gvh = ((const uint4*)g_vh) + (size_t)bh * Sc * 8;
    const uint4* gvl = ((const uint4*)g_vl) + (size_t)bh * Sc * 8;
    auto issue_tile = [&](int c, int s) {
        const uint32_t stb = sb + ASM_ST + s * ASM_STRIDE;
        const int gbase = c * 64 * 8;   // uint4 index of tile start
#pragma unroll
        for (int t = 0; t < 2; ++t) {
            const int i = t * 256 + tid;          // 0..511
            const int row = i >> 3, seg = i & 7;
            const uint32_t soff = row * 128 + ((seg ^ (row & 7)) << 4);
            CP16(stb + soff,          gkh + gbase + i);
            CP16(stb + 8192  + soff,  gkl + gbase + i);
            CP16(stb + 16384 + soff,  gvh + gbase + i);
            CP16(stb + 24576 + soff,  gvl + gbase + i);
        }
    };

    issue_tile(0, 0);
    CP_COMMIT();
    __syncthreads();   // Q smem visible

    // ---- preload Q fragments ----
    uint32_t qh[4][4], ql[4][4];
    {
        const int row = wid * 16 + (lane & 15);
#pragma unroll
        for (int ks = 0; ks < 4; ++ks) {
            const int seg = ks * 2 + (lane >> 4);
            const uint32_t soff = row * 128 + ((seg ^ (row & 7)) << 4);
            ldsm_x4(qh[ks], sb + ASM_QH + soff);
            ldsm_x4(ql[ks], sb + ASM_QL + soff);
        }
    }

    float o[8][4];
#pragma unroll
    for (int nt = 0; nt < 8; ++nt)
#pragma unroll
        for (int q = 0; q < 4; ++q) o[nt][q] = 0.f;
    float m_a = -1e30f, m_b = -1e30f, l_a = 0.f, l_b = 0.f;

    const float* arow1 = alibi + (((size_t)h * Sc) + q0 + wid * 16 + (lane >> 2)) * Sc + (lane & 3) * 2;
    const float* arow2 = arow1 + (size_t)8 * Sc;

    for (int c = 0; c < NIT; ++c) {
        if (c + 1 < NIT) {
            issue_tile(c + 1, (c + 1) & 1);
            CP_COMMIT();
            CP_WAIT(1);
        } else {
            CP_WAIT(0);
        }
        __syncthreads();

        const uint32_t st = sb + ASM_ST + (c & 1) * ASM_STRIDE;

        // ---- scores ----
        float s[8][4];
#pragma unroll
        for (int nt = 0; nt < 8; ++nt)
#pragma unroll
            for (int q = 0; q < 4; ++q) s[nt][q] = 0.f;

#pragma unroll
        for (int ks = 0; ks < 4; ++ks) {
#pragma unroll
            for (int nt = 0; nt < 8; ++nt) {
                const int row = nt * 8 + (lane & 7);
                const int seg = ks * 2 + ((lane >> 3) & 1);
                const uint32_t soff = row * 128 + ((seg ^ (row & 7)) << 4);
                uint32_t kh2[2], kl2[2];
                ldsm_x2(kh2, st + soff);
                ldsm_x2(kl2, st + 8192 + soff);
                mma16816(s[nt], qh[ks], kh2);
                mma16816(s[nt], qh[ks], kl2);
                mma16816(s[nt], ql[ks], kh2);
            }
        }

        // ---- scale + alibi + online softmax ----
        float mxa = -1e30f, mxb = -1e30f;
#pragma unroll
        for (int nt = 0; nt < 8; ++nt) {
            const float2 al1 = *(const float2*)(arow1 + (size_t)c * 64 + nt * 8);
            const float2 al2 = *(const float2*)(arow2 + (size_t)c * 64 + nt * 8);
            s[nt][0] = s[nt][0] * 0.125f + al1.x;
            s[nt][1] = s[nt][1] * 0.125f + al1.y;
            s[nt][2] = s[nt][2] * 0.125f + al2.x;
            s[nt][3] = s[nt][3] * 0.125f + al2.y;
            mxa = fmaxf(mxa, fmaxf(s[nt][0], s[nt][1]));
            mxb = fmaxf(mxb, fmaxf(s[nt][2], s[nt][3]));
        }
        mxa = fmaxf(mxa, __shfl_xor_sync(0xffffffffu, mxa, 1));
        mxa = fmaxf(mxa, __shfl_xor_sync(0xffffffffu, mxa, 2));
        mxb = fmaxf(mxb, __shfl_xor_sync(0xffffffffu, mxb, 1));
        mxb = fmaxf(mxb, __shfl_xor_sync(0xffffffffu, mxb, 2));
        const float mna = fmaxf(m_a, mxa);
        const float mnb = fmaxf(m_b, mxb);
        const float ca = __expf(m_a - mna);
        const float cb = __expf(m_b - mnb);
        float suma = 0.f, sumb = 0.f;
#pragma unroll
        for (int nt = 0; nt < 8; ++nt) {
            s[nt][0] = __expf(s[nt][0] - mna);
            s[nt][1] = __expf(s[nt][1] - mna);
            s[nt][2] = __expf(s[nt][2] - mnb);
            s[nt][3] = __expf(s[nt][3] - mnb);
            suma += s[nt][0] + s[nt][1];
            sumb += s[nt][2] + s[nt][3];
        }
        suma += __shfl_xor_sync(0xffffffffu, suma, 1);
        suma += __shfl_xor_sync(0xffffffffu, suma, 2);
        sumb += __shfl_xor_sync(0xffffffffu, sumb, 1);
        sumb += __shfl_xor_sync(0xffffffffu, sumb, 2);
        l_a = l_a * ca + suma;
        l_b = l_b * cb + sumb;
        m_a = mna; m_b = mnb;
#pragma unroll
        for (int nt = 0; nt < 8; ++nt) {
            o[nt][0] *= ca; o[nt][1] *= ca;
            o[nt][2] *= cb; o[nt][3] *= cb;
        }

        // ---- pack P fragments (C-frag -> A-frag identity) ----
        uint32_t ph[4][4], pl[4][4];
#pragma unroll
        for (int ks = 0; ks < 4; ++ks) {
            const int t0 = 2 * ks, t1 = 2 * ks + 1;
            pack_pair(s[t0][0], s[t0][1], ph[ks][0], pl[ks][0]);
            pack_pair(s[t0][2], s[t0][3], ph[ks][1], pl[ks][1]);
            pack_pair(s[t1][0], s[t1][1], ph[ks][2], pl[ks][2]);
            pack_pair(s[t1][2], s[t1][3], ph[ks][3], pl[ks][3]);
        }

        // ---- PV ----
#pragma unroll
        for (int ks = 0; ks < 4; ++ks) {
#pragma unroll
            for (int nt = 0; nt < 8; ++nt) {
                const int row = ks * 16 + (lane & 15);
                const uint32_t soff = row * 128 + ((nt ^ (row & 7)) << 4);
                uint32_t vh2[2], vl2[2];
                ldsm_x2t(vh2, st + 16384 + soff);
                ldsm_x2t(vl2, st + 24576 + soff);
                mma16816(o[nt], ph[ks], vh2);
                mma16816(o[nt], ph[ks], vl2);
                mma16816(o[nt], pl[ks], vh2);
            }
        }
        __syncthreads();
    }

    // ---- epilogue ----
    const float ia = 1.f / l_a;
    const float ib = 1.f / l_b;
    const int qa = q0 + wid * 16 + (lane >> 2);
    float* oa = g_o + ((size_t)b * Sc + qa) * Dc + h * DHc + (lane & 3) * 2;
    float* ob = oa + (size_t)8 * Dc;
#pragma unroll
    for (int nt = 0; nt < 8; ++nt) {
        *(float2*)(oa + nt * 8) = make_float2(o[nt][0] * ia, o[nt][1] * ia);
        *(float2*)(ob + nt * 8) = make_float2(o[nt][2] * ib, o[nt][3] * ib);
    }
}

// ===========================================================================
// kernel_launch: x, alibi, w_qkv, b_qkv, w_o, b_o (all fp32)
// ===========================================================================
extern "C" void kernel_launch(void* const* d_in, const int* in_sizes, int n_in,
                              void* d_out, int out_size)
{
    const float* x     = (const float*)d_in[0];
    const float* alibi = (const float*)d_in[1];
    const float* w_qkv = (const float*)d_in[2];
    const float* b_qkv = (const float*)d_in[3];
    const float* w_o   = (const float*)d_in[4];
    const float* b_o   = (const float*)d_in[5];
    float* out = (float*)d_out;

    cudaFuncSetAttribute(gemm_hmma, cudaFuncAttributeMaxDynamicSharedMemorySize, GSMEM_TOTAL);
    cudaFuncSetAttribute(attn_hmma, cudaFuncAttributeMaxDynamicSharedMemorySize, ASM_TOTAL);

    // 1) QKV projection -> split bf16 q/k/v
    {
        dim3 grid(3 * Dc / 128, Mrows / 128);   // (24, 64)
        gemm_hmma<<<grid, 256, GSMEM_TOTAL>>>(x, w_qkv, b_qkv, nullptr,
                                              Mrows, 3 * Dc, Dc, 1);
    }

    // 2) FlashAttention on HMMA
    {
        dim3 grid(Bc * Hc * (Sc / 128));         // 1024
        attn_hmma<<<grid, 256, ASM_TOTAL>>>(alibi);
    }

    // 3) Output projection
    {
        float* o_src;
        cudaGetSymbolAddress((void**)&o_src, g_o);
        dim3 grid(Dc / 128, Mrows / 128);        // (8, 64)
        gemm_hmma<<<grid, 256, GSMEM_TOTAL>>>(o_src, w_o, b_o, out,
                                              Mrows, Dc, Dc, 0);
    }
}

// round 10
// speedup vs baseline: 4.1878x; 1.0776x over previous
#include <cuda_runtime.h>
#include <cuda_bf16.h>
#include <cstdint>

// Problem constants
#define Bc 4
#define Hc 16
#define Sc 2048
#define Dc 1024
#define DHc 64
#define Mrows (Bc*Sc)          // 8192

// ---------------------------------------------------------------------------
// Scratch (device globals; allocation forbidden). All operand matrices live as
// split bf16 pairs: value = hi (trunc bf16) + lo (rn bf16 of residual).
// ---------------------------------------------------------------------------
__device__ __nv_bfloat16 g_xh[Mrows*Dc],  g_xl[Mrows*Dc];       // x split
__device__ __nv_bfloat16 g_wqh[3*Dc*Dc],  g_wql[3*Dc*Dc];       // w_qkv split
__device__ __nv_bfloat16 g_woh[Dc*Dc],    g_wol[Dc*Dc];         // w_o split
__device__ __nv_bfloat16 g_qh[Bc*Hc*Sc*DHc], g_ql[Bc*Hc*Sc*DHc];
__device__ __nv_bfloat16 g_kh[Bc*Hc*Sc*DHc], g_kl[Bc*Hc*Sc*DHc];
__device__ __nv_bfloat16 g_vh[Bc*Hc*Sc*DHc], g_vl[Bc*Hc*Sc*DHc];
__device__ __nv_bfloat16 g_oh[Mrows*Dc],  g_ol[Mrows*Dc];       // attn out split

// ===========================================================================
// Helpers
// ===========================================================================
__device__ __forceinline__ uint32_t smem_u32(const void* p) {
    uint32_t a;
    asm("{ .reg .u64 t; cvta.to.shared.u64 t, %1; cvt.u32.u64 %0, t; }"
        : "=r"(a) : "l"(p));
    return a;
}
__device__ __forceinline__ void ldsm_x4(uint32_t* r, uint32_t addr) {
    asm volatile("ldmatrix.sync.aligned.m8n8.x4.shared.b16 {%0,%1,%2,%3}, [%4];"
        : "=r"(r[0]), "=r"(r[1]), "=r"(r[2]), "=r"(r[3]) : "r"(addr));
}
__device__ __forceinline__ void ldsm_x2(uint32_t* r, uint32_t addr) {
    asm volatile("ldmatrix.sync.aligned.m8n8.x2.shared.b16 {%0,%1}, [%2];"
        : "=r"(r[0]), "=r"(r[1]) : "r"(addr));
}
__device__ __forceinline__ void ldsm_x2t(uint32_t* r, uint32_t addr) {
    asm volatile("ldmatrix.sync.aligned.m8n8.x2.trans.shared.b16 {%0,%1}, [%2];"
        : "=r"(r[0]), "=r"(r[1]) : "r"(addr));
}
__device__ __forceinline__ void mma16816(float* c, const uint32_t* a, const uint32_t* b) {
    asm volatile("mma.sync.aligned.m16n8k16.row.col.f32.bf16.bf16.f32 "
        "{%0,%1,%2,%3}, {%4,%5,%6,%7}, {%8,%9}, {%0,%1,%2,%3};"
        : "+f"(c[0]), "+f"(c[1]), "+f"(c[2]), "+f"(c[3])
        : "r"(a[0]), "r"(a[1]), "r"(a[2]), "r"(a[3]), "r"(b[0]), "r"(b[1]));
}
#define CP16(dst, src) \
    asm volatile("cp.async.cg.shared.global [%0], [%1], 16;" :: "r"(dst), "l"(src))
#define CP_COMMIT() asm volatile("cp.async.commit_group;" ::: "memory")
#define CP_WAIT(n)  asm volatile("cp.async.wait_group %0;" :: "n"(n) : "memory")

__device__ __forceinline__ void pack_pair(float a, float b, uint32_t& hi, uint32_t& lo) {
    const uint32_t ua = __float_as_uint(a), ub = __float_as_uint(b);
    hi = __byte_perm(ua, ub, 0x7632);
    const float la = a - __uint_as_float(ua & 0xFFFF0000u);
    const float lb = b - __uint_as_float(ub & 0xFFFF0000u);
    __nv_bfloat162 l2 = __floats2bfloat162_rn(la, lb);
    lo = *(uint32_t*)&l2;
}

// ===========================================================================
// Split pre-pass: fp32 -> (hi, lo) bf16 arrays. Grid-stride over float4.
// ===========================================================================
__global__ void split_kernel(const float* __restrict__ src,
                             __nv_bfloat16* __restrict__ dh,
                             __nv_bfloat16* __restrict__ dl, int n4)
{
    for (int i = blockIdx.x * blockDim.x + threadIdx.x; i < n4;
         i += gridDim.x * blockDim.x) {
        const float4 v = ((const float4*)src)[i];
        uint32_t h01, l01, h23, l23;
        pack_pair(v.x, v.y, h01, l01);
        pack_pair(v.z, v.w, h23, l23);
        ((uint2*)dh)[i] = make_uint2(h01, h23);
        ((uint2*)dl)[i] = make_uint2(l01, l23);
    }
}

// ===========================================================================
// Pure-bf16 pipelined NT GEMM (3-term virtual K): C = A*B^T + bias
// K = 1024 fixed; chunks c in [0,96): term t=c>>5 selects (Ah,Bh)/(Ah,Bl)/(Al,Bh),
// kc=c&31 is the K-chunk. 128x128 block tile, BK=32, 8 warps (2Mx4N, 64x32),
// 4-stage cp.async pipeline. SMEM/stage: A 8KB + B 8KB; total 64KB.
// Swizzle: row pair packed per 128B; conflict-free for ldmatrix + cp.async.
// mode 0: row-major fp32 C. mode 1: QKV scatter -> split bf16 q/k/v.
// ===========================================================================
#define GNC 96
#define GSTG 16384
#define GSMEM_TOTAL (4*GSTG)

__device__ __forceinline__ uint32_t gswz(int r, int seg) {
    return ((uint32_t)(r >> 1) << 7) +
           ((uint32_t)((((r & 1) << 2) | seg) ^ ((r >> 1) & 7)) << 4);
}

__global__ __launch_bounds__(256, 2)
void gemm_bf16(const __nv_bfloat16* __restrict__ Ah, const __nv_bfloat16* __restrict__ Al,
               const __nv_bfloat16* __restrict__ Bh, const __nv_bfloat16* __restrict__ Bl,
               const float* __restrict__ bias, float* __restrict__ C,
               int N, int mode)
{
    extern __shared__ char smem[];
    const uint32_t sb = smem_u32(smem);
    const int tid  = threadIdx.x;
    const int wid  = tid >> 5;
    const int lane = tid & 31;
    const int m0 = blockIdx.y * 128;
    const int n0 = blockIdx.x * 128;
    const int warpM = wid & 1;
    const int warpN = wid >> 1;

    float acc[4][4][4];
#pragma unroll
    for (int i = 0; i < 4; i++)
#pragma unroll
        for (int j = 0; j < 4; j++)
#pragma unroll
            for (int q = 0; q < 4; q++) acc[i][j][q] = 0.f;

    auto issue = [&](int c) {
        const int st = c & 3;
        const int t  = c >> 5;
        const int kc = c & 31;
        const char* Ap = (const char*)((t < 2) ? Ah : Al);
        const char* Bp = (const char*)((t == 1) ? Bl : Bh);
        const uint32_t sA = sb + st * GSTG;
        const uint32_t sB = sA + 8192;
        const size_t kb = (size_t)kc * 64;   // byte offset in row (32 bf16)
#pragma unroll
        for (int u = 0; u < 2; ++u) {
            const int i = u * 256 + tid;       // 0..511
            const int r = i >> 2;
            const int seg = i & 3;
            const uint32_t so = gswz(r, seg);
            CP16(sA + so, Ap + (size_t)(m0 + r) * 2048 + kb + seg * 16);
            CP16(sB + so, Bp + (size_t)(n0 + r) * 2048 + kb + seg * 16);
        }
    };

    issue(0); CP_COMMIT();
    issue(1); CP_COMMIT();
    issue(2); CP_COMMIT();

    for (int c = 0; c < GNC; ++c) {
        CP_WAIT(2);
        __syncthreads();

        const uint32_t sA = sb + (c & 3) * GSTG;
        const uint32_t sB = sA + 8192;

#pragma unroll
        for (int ks = 0; ks < 2; ++ks) {
            uint32_t af[4][4], bf[4][2];
#pragma unroll
            for (int mi = 0; mi < 4; ++mi) {
                const int row = warpM * 64 + mi * 16 + (lane & 15);
                const int seg = ks * 2 + (lane >> 4);
                ldsm_x4(af[mi], sA + gswz(row, seg));
            }
#pragma unroll
            for (int ni = 0; ni < 4; ++ni) {
                const int row = warpN * 32 + ni * 8 + (lane & 7);
                const int seg = ks * 2 + ((lane >> 3) & 1);
                ldsm_x2(bf[ni], sB + gswz(row, seg));
            }
#pragma unroll
            for (int mi = 0; mi < 4; ++mi)
#pragma unroll
                for (int ni = 0; ni < 4; ++ni)
                    mma16816(acc[mi][ni], af[mi], bf[ni]);
        }

        __syncthreads();
        if (c + 3 < GNC) issue(c + 3);
        CP_COMMIT();
    }

    // Epilogue
#pragma unroll
    for (int mi = 0; mi < 4; ++mi) {
#pragma unroll
        for (int ni = 0; ni < 4; ++ni) {
            const int gm = m0 + warpM * 64 + mi * 16 + (lane >> 2);
            const int gn = n0 + warpN * 32 + ni * 8 + (lane & 3) * 2;
            const float b0 = __ldg(bias + gn);
            const float b1 = __ldg(bias + gn + 1);
            float v00 = acc[mi][ni][0] + b0, v01 = acc[mi][ni][1] + b1;
            float v10 = acc[mi][ni][2] + b0, v11 = acc[mi][ni][3] + b1;
            if (mode == 0) {
                *(float2*)(C + (size_t)gm * N + gn)       = make_float2(v00, v01);
                *(float2*)(C + (size_t)(gm + 8) * N + gn) = make_float2(v10, v11);
            } else {
                const int h   = gn / 192;
                const int rmd = gn - h * 192;
                const int which = rmd >> 6;
                const int dh = rmd & 63;
                __nv_bfloat16* baseH = (which == 0) ? g_qh : (which == 1) ? g_kh : g_vh;
                __nv_bfloat16* baseL = (which == 0) ? g_ql : (which == 1) ? g_kl : g_vl;
                const int b_0 = gm >> 11, s_0 = gm & 2047;
                const int b_1 = (gm + 8) >> 11, s_1 = (gm + 8) & 2047;
                const size_t i0 = (((size_t)(b_0 * Hc + h)) * Sc + s_0) * DHc + dh;
                const size_t i1 = (((size_t)(b_1 * Hc + h)) * Sc + s_1) * DHc + dh;
                uint32_t h0, l0, h1, l1;
                pack_pair(v00, v01, h0, l0);
                pack_pair(v10, v11, h1, l1);
                *(uint32_t*)&baseH[i0] = h0;
                *(uint32_t*)&baseL[i0] = l0;
                *(uint32_t*)&baseH[i1] = h1;
                *(uint32_t*)&baseL[i1] = l1;
            }
        }
    }
}

// ===========================================================================
// HMMA FlashAttention with ALiBi — 64-query blocks (4 warps) for 2 CTAs/SM.
// K/V streamed in 64-key split-bf16 tiles via cp.async double buffer.
// Scores: QhKh+QhKl+QlKh; PV: PhVh+PhVl+PlVh. Register online softmax.
// SMEM: Qh[0,8K) Ql[8K,16K); stage s at 16K+s*32K: Kh+0 Kl+8K Vh+16K Vl+24K.
// Total 80KB. Output written as split bf16 (g_oh/g_ol).
// ===========================================================================
#define ASM_QH 0
#define ASM_QL 8192
#define ASM_ST 16384
#define ASM_STRIDE 32768
#define ASM_TOTAL 81920
#define NIT (Sc/64)     // 32

__global__ __launch_bounds__(128, 2)
void attn_hmma(const float* __restrict__ alibi)
{
    extern __shared__ char smem[];
    const uint32_t sb = smem_u32(smem);
    const int tid = threadIdx.x;
    const int wid = tid >> 5;       // 0..3
    const int lane = tid & 31;

    const int qt = blockIdx.x & 31;       // 32 query tiles of 64
    const int bh = blockIdx.x >> 5;       // 0..63
    const int h  = bh & 15;
    const int b  = bh >> 4;
    const int q0 = qt * 64;

    // ---- load Q tile (64 x 64, hi+lo) into swizzled smem ----
    {
        const uint4* gqh = ((const uint4*)g_qh) + ((size_t)bh * Sc + q0) * 8;
        const uint4* gql = ((const uint4*)g_ql) + ((size_t)bh * Sc + q0) * 8;
        for (int i = tid; i < 512; i += 128) {
            const int row = i >> 3, seg = i & 7;
            const uint32_t soff = row * 128 + ((seg ^ (row & 7)) << 4);
            *(uint4*)(smem + ASM_QH + soff) = gqh[i];
            *(uint4*)(smem + ASM_QL + soff) = gql[i];
        }
    }

    const uint4* gkh = ((const uint4*)g_kh) + (size_t)bh * Sc * 8;
    const uint4* gkl = ((const uint4*)g_kl) + (size_t)bh * Sc * 8;
    const uint4* gvh = ((const uint4*)g_vh) + (size_t)bh * Sc * 8;
    const uint4* gvl = ((const uint4*)g_vl) + (size_t)bh * Sc * 8;
    auto issue_tile = [&](int c, int s) {
        const uint32_t stb = sb + ASM_ST + s * ASM_STRIDE;
        const int gbase = c * 64 * 8;
#pragma unroll
        for (int t = 0; t < 4; ++t) {
            const int i = t * 128 + tid;          // 0..511
            const int row = i >> 3, seg = i & 7;
            const uint32_t soff = row * 128 + ((seg ^ (row & 7)) << 4);
            CP16(stb + soff,          gkh + gbase + i);
            CP16(stb + 8192  + soff,  gkl + gbase + i);
            CP16(stb + 16384 + soff,  gvh + gbase + i);
            CP16(stb + 24576 + soff,  gvl + gbase + i);
        }
    };

    issue_tile(0, 0);
    CP_COMMIT();
    __syncthreads();   // Q smem visible

    // ---- preload Q fragments ----
    uint32_t qh[4][4], ql[4][4];
    {
        const int row = wid * 16 + (lane & 15);
#pragma unroll
        for (int ks = 0; ks < 4; ++ks) {
            const int seg = ks * 2 + (lane >> 4);
            const uint32_t soff = row * 128 + ((seg ^ (row & 7)) << 4);
            ldsm_x4(qh[ks], sb + ASM_QH + soff);
            ldsm_x4(ql[ks], sb + ASM_QL + soff);
        }
    }

    float o[8][4];
#pragma unroll
    for (int nt = 0; nt < 8; ++nt)
#pragma unroll
        for (int q = 0; q < 4; ++q) o[nt][q] = 0.f;
    float m_a = -1e30f, m_b = -1e30f, l_a = 0.f, l_b = 0.f;

    const float* arow1 = alibi + (((size_t)h * Sc) + q0 + wid * 16 + (lane >> 2)) * Sc + (lane & 3) * 2;
    const float* arow2 = arow1 + (size_t)8 * Sc;

    for (int c = 0; c < NIT; ++c) {
        if (c + 1 < NIT) {
            issue_tile(c + 1, (c + 1) & 1);
            CP_COMMIT();
            CP_WAIT(1);
        } else {
            CP_WAIT(0);
        }
        __syncthreads();

        const uint32_t st = sb + ASM_ST + (c & 1) * ASM_STRIDE;

        // ---- scores ----
        float s[8][4];
#pragma unroll
        for (int nt = 0; nt < 8; ++nt)
#pragma unroll
            for (int q = 0; q < 4; ++q) s[nt][q] = 0.f;

#pragma unroll
        for (int ks = 0; ks < 4; ++ks) {
#pragma unroll
            for (int nt = 0; nt < 8; ++nt) {
                const int row = nt * 8 + (lane & 7);
                const int seg = ks * 2 + ((lane >> 3) & 1);
                const uint32_t soff = row * 128 + ((seg ^ (row & 7)) << 4);
                uint32_t kh2[2], kl2[2];
                ldsm_x2(kh2, st + soff);
                ldsm_x2(kl2, st + 8192 + soff);
                mma16816(s[nt], qh[ks], kh2);
                mma16816(s[nt], qh[ks], kl2);
                mma16816(s[nt], ql[ks], kh2);
            }
        }

        // ---- scale + alibi + online softmax ----
        float mxa = -1e30f, mxb = -1e30f;
#pragma unroll
        for (int nt = 0; nt < 8; ++nt) {
            const float2 al1 = *(const float2*)(arow1 + (size_t)c * 64 + nt * 8);
            const float2 al2 = *(const float2*)(arow2 + (size_t)c * 64 + nt * 8);
            s[nt][0] = s[nt][0] * 0.125f + al1.x;
            s[nt][1] = s[nt][1] * 0.125f + al1.y;
            s[nt][2] = s[nt][2] * 0.125f + al2.x;
            s[nt][3] = s[nt][3] * 0.125f + al2.y;
            mxa = fmaxf(mxa, fmaxf(s[nt][0], s[nt][1]));
            mxb = fmaxf(mxb, fmaxf(s[nt][2], s[nt][3]));
        }
        mxa = fmaxf(mxa, __shfl_xor_sync(0xffffffffu, mxa, 1));
        mxa = fmaxf(mxa, __shfl_xor_sync(0xffffffffu, mxa, 2));
        mxb = fmaxf(mxb, __shfl_xor_sync(0xffffffffu, mxb, 1));
        mxb = fmaxf(mxb, __shfl_xor_sync(0xffffffffu, mxb, 2));
        const float mna = fmaxf(m_a, mxa);
        const float mnb = fmaxf(m_b, mxb);
        const float ca = __expf(m_a - mna);
        const float cb = __expf(m_b - mnb);
        float suma = 0.f, sumb = 0.f;
#pragma unroll
        for (int nt = 0; nt < 8; ++nt) {
            s[nt][0] = __expf(s[nt][0] - mna);
            s[nt][1] = __expf(s[nt][1] - mna);
            s[nt][2] = __expf(s[nt][2] - mnb);
            s[nt][3] = __expf(s[nt][3] - mnb);
            suma += s[nt][0] + s[nt][1];
            sumb += s[nt][2] + s[nt][3];
        }
        suma += __shfl_xor_sync(0xffffffffu, suma, 1);
        suma += __shfl_xor_sync(0xffffffffu, suma, 2);
        sumb += __shfl_xor_sync(0xffffffffu, sumb, 1);
        sumb += __shfl_xor_sync(0xffffffffu, sumb, 2);
        l_a = l_a * ca + suma;
        l_b = l_b * cb + sumb;
        m_a = mna; m_b = mnb;
#pragma unroll
        for (int nt = 0; nt < 8; ++nt) {
            o[nt][0] *= ca; o[nt][1] *= ca;
            o[nt][2] *= cb; o[nt][3] *= cb;
        }

        // ---- pack P fragments (C-frag -> A-frag identity) ----
        uint32_t ph[4][4], pl[4][4];
#pragma unroll
        for (int ks = 0; ks < 4; ++ks) {
            const int t0 = 2 * ks, t1 = 2 * ks + 1;
            pack_pair(s[t0][0], s[t0][1], ph[ks][0], pl[ks][0]);
            pack_pair(s[t0][2], s[t0][3], ph[ks][1], pl[ks][1]);
            pack_pair(s[t1][0], s[t1][1], ph[ks][2], pl[ks][2]);
            pack_pair(s[t1][2], s[t1][3], ph[ks][3], pl[ks][3]);
        }

        // ---- PV ----
#pragma unroll
        for (int ks = 0; ks < 4; ++ks) {
#pragma unroll
            for (int nt = 0; nt < 8; ++nt) {
                const int row = ks * 16 + (lane & 15);
                const uint32_t soff = row * 128 + ((nt ^ (row & 7)) << 4);
                uint32_t vh2[2], vl2[2];
                ldsm_x2t(vh2, st + 16384 + soff);
                ldsm_x2t(vl2, st + 24576 + soff);
                mma16816(o[nt], ph[ks], vh2);
                mma16816(o[nt], ph[ks], vl2);
                mma16816(o[nt], pl[ks], vh2);
            }
        }
        __syncthreads();
    }

    // ---- epilogue: write split bf16 output ----
    const float ia = 1.f / l_a;
    const float ib = 1.f / l_b;
    const int qa = q0 + wid * 16 + (lane >> 2);
    const size_t i0 = ((size_t)b * Sc + qa) * Dc + h * DHc + (lane & 3) * 2;
    const size_t i1 = i0 + (size_t)8 * Dc;
#pragma unroll
    for (int nt = 0; nt < 8; ++nt) {
        uint32_t hA, lA, hB, lB;
        pack_pair(o[nt][0] * ia, o[nt][1] * ia, hA, lA);
        pack_pair(o[nt][2] * ib, o[nt][3] * ib, hB, lB);
        *(uint32_t*)&g_oh[i0 + nt * 8] = hA;
        *(uint32_t*)&g_ol[i0 + nt * 8] = lA;
        *(uint32_t*)&g_oh[i1 + nt * 8] = hB;
        *(uint32_t*)&g_ol[i1 + nt * 8] = lB;
    }
}

// ===========================================================================
// kernel_launch: x, alibi, w_qkv, b_qkv, w_o, b_o (all fp32)
// ===========================================================================
extern "C" void kernel_launch(void* const* d_in, const int* in_sizes, int n_in,
                              void* d_out, int out_size)
{
    const float* x     = (const float*)d_in[0];
    const float* alibi = (const float*)d_in[1];
    const float* w_qkv = (const float*)d_in[2];
    const float* b_qkv = (const float*)d_in[3];
    const float* w_o   = (const float*)d_in[4];
    const float* b_o   = (const float*)d_in[5];
    float* out = (float*)d_out;

    cudaFuncSetAttribute(gemm_bf16, cudaFuncAttributeMaxDynamicSharedMemorySize, GSMEM_TOTAL);
    cudaFuncSetAttribute(attn_hmma, cudaFuncAttributeMaxDynamicSharedMemorySize, ASM_TOTAL);

    __nv_bfloat16 *xh, *xl, *wqh, *wql, *woh, *wol, *oh, *ol;
    cudaGetSymbolAddress((void**)&xh,  g_xh);
    cudaGetSymbolAddress((void**)&xl,  g_xl);
    cudaGetSymbolAddress((void**)&wqh, g_wqh);
    cudaGetSymbolAddress((void**)&wql, g_wql);
    cudaGetSymbolAddress((void**)&woh, g_woh);
    cudaGetSymbolAddress((void**)&wol, g_wol);
    cudaGetSymbolAddress((void**)&oh,  g_oh);
    cudaGetSymbolAddress((void**)&ol,  g_ol);

    // 0) split pre-pass
    split_kernel<<<1024, 256>>>(x,     xh,  xl,  Mrows * Dc / 4);
    split_kernel<<<512,  256>>>(w_qkv, wqh, wql, 3 * Dc * Dc / 4);
    split_kernel<<<256,  256>>>(w_o,   woh, wol, Dc * Dc / 4);

    // 1) QKV projection -> split bf16 q/k/v
    {
        dim3 grid(3 * Dc / 128, Mrows / 128);   // (24, 64)
        gemm_bf16<<<grid, 256, GSMEM_TOTAL>>>(xh, xl, wqh, wql, b_qkv, nullptr,
                                              3 * Dc, 1);
    }

    // 2) FlashAttention on HMMA (64-query blocks)
    {
        dim3 grid(Bc * Hc * (Sc / 64));          // 2048
        attn_hmma<<<grid, 128, ASM_TOTAL>>>(alibi);
    }

    // 3) Output projection
    {
        dim3 grid(Dc / 128, Mrows / 128);        // (8, 64)
        gemm_bf16<<<grid, 256, GSMEM_TOTAL>>>(oh, ol, woh, wol, b_o, out,
                                              Dc, 0);
    }
}